// round 2
// baseline (speedup 1.0000x reference)
#include <cuda_runtime.h>

// Problem constants (fixed by the reference)
#define HH  512
#define WW  512
#define CC  32
#define BB  2
#define NLp 50000
#define NRp 20000
#define EPSf 1e-5f
#define FULLMASK 0xffffffffu

// ---------------------------------------------------------------------------
// Folded parameter block per attention branch.
// All 32x32 matrices stored TRANSPOSED ([m][o]) so lane o reads coalesced.
// ---------------------------------------------------------------------------
struct Folded {
    float WqT[CC * CC]; float bq[CC];                    // query path (LN -> q proj -> in-proj q)
    float WkT[CC * CC]; float bkv[CC]; float bki[CC];    // key path; bki = bias for invalid slot
    float WvT[CC * CC]; float bvv[CC]; float bvi[CC];    // value path
    float pe9v[9 * CC];                                  // Wiv @ pe9[j]  (added for valid slots)
    float WoT[CC * CC]; float bo[CC];                    // out projection (transposed)
};

__device__ Folded g_f1, g_f2;
__device__ int   g_grid_li[BB * HH * WW];
__device__ int   g_grid_ra[BB * HH * WW];
__device__ float g_qp1[BB * (size_t)NLp * CC];   // branch1 queries  (lidar)
__device__ float g_kk2[BB * (size_t)NLp * CC];   // branch2 keys     (lidar)
__device__ float g_vv2[BB * (size_t)NLp * CC];   // branch2 values   (lidar)
__device__ float g_qp2[BB * (size_t)NRp * CC];   // branch2 queries  (radar)
__device__ float g_kk1[BB * (size_t)NRp * CC];   // branch1 keys     (radar)
__device__ float g_vv1[BB * (size_t)NRp * CC];   // branch1 values   (radar)
__device__ unsigned char g_dym[BB * NLp];
__device__ unsigned int  g_dyflags;              // bit0: saw byte>=2 (32-bit), bit1: saw hi-byte in {1}

__constant__ int SH9[9][2] = {
    {0,0},{-1,0},{1,0},{0,1},{-1,1},{1,1},{0,-1},{-1,-1},{1,-1}
};

// ---------------------------------------------------------------------------
// Weight folding (tiny: one block)
// ---------------------------------------------------------------------------
struct Params {
    const float *q1w,*q1b,*k1w,*k1b,*v1w,*v1b;
    const float *q2w,*q2b,*k2w,*k2b,*v2w,*v2b;
    const float *posw,*posb;
    const float *a1iw,*a1ib,*a1ow,*a1ob;
    const float *a2iw,*a2ib,*a2ow,*a2ob;
};

__device__ void fold_branch(Folded* f,
                            const float* qw, const float* qb,
                            const float* kw, const float* kb,
                            const float* vw, const float* vb,
                            const float* inw, const float* inb,
                            const float* ow,  const float* ob,
                            const float* posw, const float* posb,
                            int o, int m)
{
    float aq = 0.f, ak = 0.f, av = 0.f;
    #pragma unroll
    for (int i = 0; i < CC; i++) {
        aq += inw[o * CC + i]            * qw[i * CC + m];
        ak += inw[(CC + o) * CC + i]     * kw[i * CC + m];
        av += inw[(2 * CC + o) * CC + i] * vw[i * CC + m];
    }
    f->WqT[m * CC + o] = aq;
    f->WkT[m * CC + o] = ak;
    f->WvT[m * CC + o] = av;
    f->WoT[m * CC + o] = ow[o * CC + m];   // transpose of out weight

    if (m == 0) {
        float bq = inb[o], bk = inb[CC + o], bv = inb[2 * CC + o];
        #pragma unroll
        for (int i = 0; i < CC; i++) {
            bq += inw[o * CC + i]            * qb[i];
            bk += inw[(CC + o) * CC + i]     * kb[i];
            bv += inw[(2 * CC + o) * CC + i] * vb[i];
        }
        f->bq[o]  = bq;
        f->bkv[o] = bk;  f->bki[o] = inb[CC + o];
        f->bvv[o] = bv;  f->bvi[o] = inb[2 * CC + o];
        f->bo[o]  = ob[o];
    }
    if (m < 9) {
        float s0 = (float)SH9[m][0], s1 = (float)SH9[m][1];
        float acc = 0.f;
        #pragma unroll
        for (int i = 0; i < CC; i++) {
            float pe = s0 * posw[i * 2] + s1 * posw[i * 2 + 1] + posb[i];
            acc += inw[(2 * CC + o) * CC + i] * pe;
        }
        f->pe9v[m * CC + o] = acc;
    }
}

__global__ void prep_kernel(Params P)
{
    int tid = threadIdx.x;
    int o = tid >> 5, m = tid & 31;
    fold_branch(&g_f1, P.q1w, P.q1b, P.k1w, P.k1b, P.v1w, P.v1b,
                P.a1iw, P.a1ib, P.a1ow, P.a1ob, P.posw, P.posb, o, m);
    fold_branch(&g_f2, P.q2w, P.q2b, P.k2w, P.k2b, P.v2w, P.v2b,
                P.a2iw, P.a2ib, P.a2ow, P.a2ob, P.posw, P.posb, o, m);
    if (tid == 0) g_dyflags = 0;
}

// ---------------------------------------------------------------------------
// dy dtype probe: scan first 10000 u32 words (safe for 1-byte bool layout:
// 40000 bytes == 10000 words). Classify layout:
//   any byte >= 2           -> 32-bit elements (float32 pattern 3f 80 00 00)
//   else any hi-byte == 1   -> uint8/bool elements
//   else                    -> int32 elements (words are 0/1)
// ---------------------------------------------------------------------------
__global__ void dy_probe_kernel(const unsigned int* __restrict__ p)
{
    unsigned int f = 0;
    for (int i = blockIdx.x * blockDim.x + threadIdx.x; i < (BB * NRp) / 4;
         i += blockDim.x * gridDim.x) {
        unsigned int w = p[i];
        unsigned int b0 = w & 0xffu, b1 = (w >> 8) & 0xffu,
                     b2 = (w >> 16) & 0xffu, b3 = (w >> 24) & 0xffu;
        if (b0 >= 2u || b1 >= 2u || b2 >= 2u || b3 >= 2u) f |= 1u;
        if ((w & 0xffffff00u) != 0u) f |= 2u;
    }
    // warp + block reduce via atomic (tiny kernel, cost irrelevant)
    if (f) atomicOr(&g_dyflags, f);
}

// ---------------------------------------------------------------------------
// Grid / mask reset + build
// ---------------------------------------------------------------------------
__global__ void clear_kernel()
{
    int i = blockIdx.x * blockDim.x + threadIdx.x;
    if (i < BB * HH * WW) { g_grid_li[i] = -1; g_grid_ra[i] = -1; }
    if (i < BB * NLp) g_dym[i] = 0;
}

__global__ void build_grid_kernel(const int* __restrict__ coors, int N, int which_li)
{
    int i = blockIdx.x * blockDim.x + threadIdx.x;
    if (i >= BB * N) return;
    int b = i / N;
    int x = coors[i * 2], y = coors[i * 2 + 1];
    int* grid = which_li ? g_grid_li : g_grid_ra;
    grid[b * HH * WW + x * WW + y] = i - b * N;
}

// ---------------------------------------------------------------------------
// Fused LayerNorm + three folded 32x32 matvecs; one warp per pillar,
// lane == channel.
// ---------------------------------------------------------------------------
__global__ void proj_kernel(const float* __restrict__ feats, int N,
                            const float* __restrict__ lnw,
                            const float* __restrict__ lnb,
                            int lidar)
{
    int gw   = (blockIdx.x * blockDim.x + threadIdx.x) >> 5;
    int lane = threadIdx.x & 31;
    if (gw >= BB * N) return;

    const Folded* fq  = lidar ? &g_f1 : &g_f2;   // queries use own branch
    const Folded* fkv = lidar ? &g_f2 : &g_f1;   // k/v feed the other branch
    float* qp = lidar ? g_qp1 : g_qp2;
    float* kk = lidar ? g_kk2 : g_kk1;
    float* vv = lidar ? g_vv2 : g_vv1;

    float v = feats[(size_t)gw * CC + lane];
    float s = v;
    #pragma unroll
    for (int off = 16; off; off >>= 1) s += __shfl_xor_sync(FULLMASK, s, off);
    float mu = s * (1.f / 32.f);
    float d  = v - mu;
    float ss = d * d;
    #pragma unroll
    for (int off = 16; off; off >>= 1) ss += __shfl_xor_sync(FULLMASK, ss, off);
    float xn = d * rsqrtf(ss * (1.f / 32.f) + EPSf) * lnw[lane] + lnb[lane];

    float aq = fq->bq[lane], ak = fkv->bkv[lane], av = fkv->bvv[lane];
    #pragma unroll
    for (int m = 0; m < CC; m++) {
        float xm = __shfl_sync(FULLMASK, xn, m);
        aq = fmaf(fq->WqT[m * CC + lane],  xm, aq);
        ak = fmaf(fkv->WkT[m * CC + lane], xm, ak);
        av = fmaf(fkv->WvT[m * CC + lane], xm, av);
    }
    size_t o = (size_t)gw * CC + lane;
    qp[o] = aq; kk[o] = ak; vv[o] = av;
}

// ---------------------------------------------------------------------------
// Dynamic-lidar mask: 5x5 window around each dynamic radar pillar, with the
// reference's mod-(H+1,W+1) wraparound quirk reproduced exactly.
// dy buffer read adaptively per probed layout.
// ---------------------------------------------------------------------------
__global__ void dy_kernel(const int* __restrict__ ra_coors,
                          const void* __restrict__ dy)
{
    int t = blockIdx.x * blockDim.x + threadIdx.x;
    if (t >= BB * NRp * 25) return;
    int s = t % 25;
    int r = t / 25;

    unsigned int flags = g_dyflags;
    bool is_dy;
    if (flags & 1u) {
        // 32-bit elements (float32 1.0f or any nonzero 32-bit int)
        is_dy = ((const unsigned int*)dy)[r] != 0u;
    } else if (flags & 2u) {
        // uint8/bool elements
        is_dy = ((const unsigned char*)dy)[r] != 0;
    } else {
        // int32 elements with values 0/1
        is_dy = ((const unsigned int*)dy)[r] != 0u;
    }
    if (!is_dy) return;

    int b  = r / NRp;
    int nx = ra_coors[r * 2]     + (s / 5) - 2;
    int ny = ra_coors[r * 2 + 1] + (s % 5) - 2;
    nx = nx < 0 ? nx + (HH + 1) : (nx >= (HH + 1) ? nx - (HH + 1) : nx);
    ny = ny < 0 ? ny + (WW + 1) : (ny >= (WW + 1) ? ny - (WW + 1) : ny);
    if (nx >= HH || ny >= WW) return;
    int idx = g_grid_li[b * HH * WW + nx * WW + ny];
    if (idx >= 0) g_dym[b * NLp + idx] = 1;
}

// ---------------------------------------------------------------------------
// Output zero-fill (d_out is poisoned before timing)
// ---------------------------------------------------------------------------
__global__ void zero_kernel(float4* __restrict__ out, long n4)
{
    long i = blockIdx.x * (long)blockDim.x + threadIdx.x;
    if (i < n4) out[i] = make_float4(0.f, 0.f, 0.f, 0.f);
}

// ---------------------------------------------------------------------------
// Cross attention: one warp per query pillar, lane == channel.
// 2 heads x 16 dims: head dot via 16-lane xor butterfly. 9 keys, no key
// masking in softmax (invalid slots contribute the in-proj bias, as in ref).
// ---------------------------------------------------------------------------
__global__ void attn_kernel(const int* __restrict__ coors, int N, int M,
                            int branch1, float* __restrict__ out)
{
    int gw   = (blockIdx.x * blockDim.x + threadIdx.x) >> 5;
    int lane = threadIdx.x & 31;
    if (gw >= BB * N) return;
    if (branch1 && !g_dym[gw]) return;   // masked pillar -> canvas stays zero

    const Folded* f = branch1 ? &g_f1 : &g_f2;
    const int*   grid = branch1 ? g_grid_ra : g_grid_li;
    const float* qp   = branch1 ? g_qp1 : g_qp2;
    const float* kk   = branch1 ? g_kk1 : g_kk2;
    const float* vv   = branch1 ? g_vv1 : g_vv2;

    int b  = gw / N;
    int cx = coors[gw * 2], cy = coors[gw * 2 + 1];
    float q = qp[(size_t)gw * CC + lane];
    const int*   gb  = grid + b * HH * WW;
    const float* kkb = kk + (size_t)b * M * CC;
    const float* vvb = vv + (size_t)b * M * CC;

    float sj[9], vpj[9];
    #pragma unroll
    for (int j = 0; j < 9; j++) {
        int nx = cx + SH9[j][0], ny = cy + SH9[j][1];
        int idx = -1;
        if ((unsigned)nx < HH && (unsigned)ny < WW) idx = gb[nx * WW + ny];
        float kp, vp;
        if (idx >= 0) {
            kp = kkb[(size_t)idx * CC + lane];
            vp = vvb[(size_t)idx * CC + lane] + f->pe9v[j * CC + lane];
        } else {
            kp = f->bki[lane];
            vp = f->bvi[lane];
        }
        float pr = q * kp;                          // head dot: reduce 16 lanes
        pr += __shfl_xor_sync(FULLMASK, pr, 8);
        pr += __shfl_xor_sync(FULLMASK, pr, 4);
        pr += __shfl_xor_sync(FULLMASK, pr, 2);
        pr += __shfl_xor_sync(FULLMASK, pr, 1);
        sj[j]  = pr * 0.25f;                        // 1/sqrt(16)
        vpj[j] = vp;
    }

    float mx = sj[0];
    #pragma unroll
    for (int j = 1; j < 9; j++) mx = fmaxf(mx, sj[j]);
    float den = 0.f, o = 0.f;
    #pragma unroll
    for (int j = 0; j < 9; j++) {
        float e = expf(sj[j] - mx);
        den += e;
        o = fmaf(e, vpj[j], o);
    }
    o /= den;

    float acc = f->bo[lane];
    #pragma unroll
    for (int l = 0; l < CC; l++) {
        float ol = __shfl_sync(FULLMASK, o, l);
        acc = fmaf(f->WoT[l * CC + lane], ol, acc);
    }
    out[(((size_t)b * CC + lane) * HH + cx) * WW + cy] = acc;
}

// ---------------------------------------------------------------------------
// Host launcher
// ---------------------------------------------------------------------------
extern "C" void kernel_launch(void* const* d_in, const int* in_sizes, int n_in,
                              void* d_out, int out_size)
{
    const float* li_f = (const float*)d_in[0];
    const int*   li_c = (const int*)d_in[1];
    const float* ra_f = (const float*)d_in[2];
    const int*   ra_c = (const int*)d_in[3];
    const void*  dy   = d_in[4];
    const float* ln_li_w = (const float*)d_in[5];
    const float* ln_li_b = (const float*)d_in[6];
    const float* ln_ra_w = (const float*)d_in[7];
    const float* ln_ra_b = (const float*)d_in[8];

    Params P;
    P.q1w = (const float*)d_in[9];   P.q1b = (const float*)d_in[10];
    P.k1w = (const float*)d_in[11];  P.k1b = (const float*)d_in[12];
    P.v1w = (const float*)d_in[13];  P.v1b = (const float*)d_in[14];
    P.q2w = (const float*)d_in[15];  P.q2b = (const float*)d_in[16];
    P.k2w = (const float*)d_in[17];  P.k2b = (const float*)d_in[18];
    P.v2w = (const float*)d_in[19];  P.v2b = (const float*)d_in[20];
    P.posw = (const float*)d_in[21]; P.posb = (const float*)d_in[22];
    P.a1iw = (const float*)d_in[23]; P.a1ib = (const float*)d_in[24];
    P.a1ow = (const float*)d_in[25]; P.a1ob = (const float*)d_in[26];
    P.a2iw = (const float*)d_in[27]; P.a2ib = (const float*)d_in[28];
    P.a2ow = (const float*)d_in[29]; P.a2ob = (const float*)d_in[30];

    float* out = (float*)d_out;

    // 1. fold weights (+ reset dy probe flags)
    prep_kernel<<<1, 1024>>>(P);

    // 2. probe dy dtype + clear grids/mask
    dy_probe_kernel<<<10, 256>>>((const unsigned int*)dy);
    clear_kernel<<<(BB * HH * WW + 255) / 256, 256>>>();

    // 3. build coord->pillar grids
    build_grid_kernel<<<(BB * NLp + 255) / 256, 256>>>(li_c, NLp, 1);
    build_grid_kernel<<<(BB * NRp + 255) / 256, 256>>>(ra_c, NRp, 0);

    // 4. projection maps (warp per pillar => 32 threads per pillar)
    proj_kernel<<<(BB * NLp * 32 + 255) / 256, 256>>>(li_f, NLp, ln_li_w, ln_li_b, 1);
    proj_kernel<<<(BB * NRp * 32 + 255) / 256, 256>>>(ra_f, NRp, ln_ra_w, ln_ra_b, 0);

    // 5. dynamic lidar mask
    dy_kernel<<<(BB * NRp * 25 + 255) / 256, 256>>>(ra_c, dy);

    // 6. zero the output canvases
    long n4 = (long)out_size / 4;
    zero_kernel<<<(int)((n4 + 255) / 256), 256>>>((float4*)out, n4);

    // 7. attention branches
    size_t img_elems = (size_t)BB * CC * HH * WW;
    attn_kernel<<<(BB * NLp * 32 + 255) / 256, 256>>>(li_c, NLp, NRp, 1, out);
    attn_kernel<<<(BB * NRp * 32 + 255) / 256, 256>>>(ra_c, NRp, NLp, 0, out + img_elems);
}

// round 3
// speedup vs baseline: 1.0883x; 1.0883x over previous
#include <cuda_runtime.h>

#define HH  512
#define WW  512
#define CC  32
#define BB  2
#define NLp 50000
#define NRp 20000
#define EPSf 1e-5f
#define FULLMASK 0xffffffffu

// ---------------------------------------------------------------------------
// Folded parameter block per attention branch (matrices transposed [m][o]).
// ---------------------------------------------------------------------------
struct Folded {
    float WqT[CC * CC]; float bq[CC];
    float WkT[CC * CC]; float bkv[CC]; float bki[CC];
    float WvT[CC * CC]; float bvv[CC]; float bvi[CC];
    float pe9v[9 * CC];
    float WoT[CC * CC]; float bo[CC];
};

__device__ Folded g_f1, g_f2;
__device__ int   g_grid_li[BB * HH * WW];
__device__ int   g_grid_ra[BB * HH * WW];
__device__ float g_qp1[BB * (size_t)NLp * CC];
__device__ float g_kk2[BB * (size_t)NLp * CC];
__device__ float g_vv2[BB * (size_t)NLp * CC];
__device__ float g_qp2[BB * (size_t)NRp * CC];
__device__ float g_kk1[BB * (size_t)NRp * CC];
__device__ float g_vv1[BB * (size_t)NRp * CC];
__device__ float g_out1[BB * (size_t)NLp * CC];   // compact branch1 output
__device__ float g_out2[BB * (size_t)NRp * CC];   // compact branch2 output
__device__ unsigned char g_dym[BB * NLp];
__device__ unsigned int  g_dyflags;

__constant__ int SH9[9][2] = {
    {0,0},{-1,0},{1,0},{0,1},{-1,1},{1,1},{0,-1},{-1,-1},{1,-1}
};

struct Params {
    const float *q1w,*q1b,*k1w,*k1b,*v1w,*v1b;
    const float *q2w,*q2b,*k2w,*k2b,*v2w,*v2b;
    const float *posw,*posb;
    const float *a1iw,*a1ib,*a1ow,*a1ob;
    const float *a2iw,*a2ib,*a2ow,*a2ob;
};

__device__ void fold_branch(Folded* f,
                            const float* qw, const float* qb,
                            const float* kw, const float* kb,
                            const float* vw, const float* vb,
                            const float* inw, const float* inb,
                            const float* ow,  const float* ob,
                            const float* posw, const float* posb,
                            int o, int m)
{
    float aq = 0.f, ak = 0.f, av = 0.f;
    #pragma unroll
    for (int i = 0; i < CC; i++) {
        aq += inw[o * CC + i]            * qw[i * CC + m];
        ak += inw[(CC + o) * CC + i]     * kw[i * CC + m];
        av += inw[(2 * CC + o) * CC + i] * vw[i * CC + m];
    }
    f->WqT[m * CC + o] = aq;
    f->WkT[m * CC + o] = ak;
    f->WvT[m * CC + o] = av;
    f->WoT[m * CC + o] = ow[o * CC + m];

    if (m == 0) {
        float bq = inb[o], bk = inb[CC + o], bv = inb[2 * CC + o];
        #pragma unroll
        for (int i = 0; i < CC; i++) {
            bq += inw[o * CC + i]            * qb[i];
            bk += inw[(CC + o) * CC + i]     * kb[i];
            bv += inw[(2 * CC + o) * CC + i] * vb[i];
        }
        f->bq[o]  = bq;
        f->bkv[o] = bk;  f->bki[o] = inb[CC + o];
        f->bvv[o] = bv;  f->bvi[o] = inb[2 * CC + o];
        f->bo[o]  = ob[o];
    }
    if (m < 9) {
        float s0 = (float)SH9[m][0], s1 = (float)SH9[m][1];
        float acc = 0.f;
        #pragma unroll
        for (int i = 0; i < CC; i++) {
            float pe = s0 * posw[i * 2] + s1 * posw[i * 2 + 1] + posb[i];
            acc += inw[(2 * CC + o) * CC + i] * pe;
        }
        f->pe9v[m * CC + o] = acc;
    }
}

__global__ void prep_kernel(Params P)
{
    int tid = threadIdx.x;
    int o = tid >> 5, m = tid & 31;
    fold_branch(&g_f1, P.q1w, P.q1b, P.k1w, P.k1b, P.v1w, P.v1b,
                P.a1iw, P.a1ib, P.a1ow, P.a1ob, P.posw, P.posb, o, m);
    fold_branch(&g_f2, P.q2w, P.q2b, P.k2w, P.k2b, P.v2w, P.v2b,
                P.a2iw, P.a2ib, P.a2ow, P.a2ob, P.posw, P.posb, o, m);
    if (tid == 0) g_dyflags = 0;
}

// dy dtype probe (see R1): classify bool buffer layout from its bytes.
__global__ void dy_probe_kernel(const unsigned int* __restrict__ p)
{
    unsigned int f = 0;
    for (int i = blockIdx.x * blockDim.x + threadIdx.x; i < (BB * NRp) / 4;
         i += blockDim.x * gridDim.x) {
        unsigned int w = p[i];
        unsigned int b0 = w & 0xffu, b1 = (w >> 8) & 0xffu,
                     b2 = (w >> 16) & 0xffu, b3 = (w >> 24) & 0xffu;
        if (b0 >= 2u || b1 >= 2u || b2 >= 2u || b3 >= 2u) f |= 1u;
        if ((w & 0xffffff00u) != 0u) f |= 2u;
    }
    if (f) atomicOr(&g_dyflags, f);
}

__global__ void clear_kernel()
{
    int i = blockIdx.x * blockDim.x + threadIdx.x;
    if (i < BB * HH * WW) { g_grid_li[i] = -1; g_grid_ra[i] = -1; }
    if (i < BB * NLp) g_dym[i] = 0;
}

// Fused: first BB*NLp threads build lidar grid, rest build radar grid.
__global__ void build_grid_kernel(const int* __restrict__ li_c,
                                  const int* __restrict__ ra_c)
{
    int i = blockIdx.x * blockDim.x + threadIdx.x;
    if (i < BB * NLp) {
        int b = i / NLp;
        g_grid_li[b * HH * WW + li_c[i * 2] * WW + li_c[i * 2 + 1]] = i - b * NLp;
    } else if (i < BB * (NLp + NRp)) {
        int j = i - BB * NLp;
        int b = j / NRp;
        g_grid_ra[b * HH * WW + ra_c[j * 2] * WW + ra_c[j * 2 + 1]] = j - b * NRp;
    }
}

// ---------------------------------------------------------------------------
// Fused LN + 3 folded matvecs for both modalities; warp per pillar.
// ---------------------------------------------------------------------------
__global__ void proj_kernel(const float* __restrict__ li_f,
                            const float* __restrict__ ra_f,
                            const float* __restrict__ ln_li_w,
                            const float* __restrict__ ln_li_b,
                            const float* __restrict__ ln_ra_w,
                            const float* __restrict__ ln_ra_b)
{
    int gw   = (blockIdx.x * blockDim.x + threadIdx.x) >> 5;
    int lane = threadIdx.x & 31;
    if (gw >= BB * (NLp + NRp)) return;

    int lidar = gw < BB * NLp;
    int p = lidar ? gw : gw - BB * NLp;

    const float* feats = lidar ? li_f : ra_f;
    const float* lnw   = lidar ? ln_li_w : ln_ra_w;
    const float* lnb   = lidar ? ln_li_b : ln_ra_b;
    const Folded* fq   = lidar ? &g_f1 : &g_f2;
    const Folded* fkv  = lidar ? &g_f2 : &g_f1;
    float* qp = lidar ? g_qp1 : g_qp2;
    float* kk = lidar ? g_kk2 : g_kk1;
    float* vv = lidar ? g_vv2 : g_vv1;

    float v = feats[(size_t)p * CC + lane];
    float s = v;
    #pragma unroll
    for (int off = 16; off; off >>= 1) s += __shfl_xor_sync(FULLMASK, s, off);
    float mu = s * (1.f / 32.f);
    float d  = v - mu;
    float ss = d * d;
    #pragma unroll
    for (int off = 16; off; off >>= 1) ss += __shfl_xor_sync(FULLMASK, ss, off);
    float xn = d * rsqrtf(ss * (1.f / 32.f) + EPSf) * lnw[lane] + lnb[lane];

    float aq = fq->bq[lane], ak = fkv->bkv[lane], av = fkv->bvv[lane];
    #pragma unroll
    for (int m = 0; m < CC; m++) {
        float xm = __shfl_sync(FULLMASK, xn, m);
        aq = fmaf(fq->WqT[m * CC + lane],  xm, aq);
        ak = fmaf(fkv->WkT[m * CC + lane], xm, ak);
        av = fmaf(fkv->WvT[m * CC + lane], xm, av);
    }
    size_t o = (size_t)p * CC + lane;
    qp[o] = aq; kk[o] = ak; vv[o] = av;
}

// ---------------------------------------------------------------------------
// Dynamic-lidar mask (5x5 window, mod-(H+1,W+1) wraparound quirk preserved).
// ---------------------------------------------------------------------------
__global__ void dy_kernel(const int* __restrict__ ra_coors,
                          const void* __restrict__ dy)
{
    int t = blockIdx.x * blockDim.x + threadIdx.x;
    if (t >= BB * NRp * 25) return;
    int s = t % 25;
    int r = t / 25;

    unsigned int flags = g_dyflags;
    bool is_dy;
    if (flags & 1u)      is_dy = ((const unsigned int*)dy)[r] != 0u;
    else if (flags & 2u) is_dy = ((const unsigned char*)dy)[r] != 0;
    else                 is_dy = ((const unsigned int*)dy)[r] != 0u;
    if (!is_dy) return;

    int b  = r / NRp;
    int nx = ra_coors[r * 2]     + (s / 5) - 2;
    int ny = ra_coors[r * 2 + 1] + (s % 5) - 2;
    nx = nx < 0 ? nx + (HH + 1) : (nx >= (HH + 1) ? nx - (HH + 1) : nx);
    ny = ny < 0 ? ny + (WW + 1) : (ny >= (WW + 1) ? ny - (WW + 1) : ny);
    if (nx >= HH || ny >= WW) return;
    int idx = g_grid_li[b * HH * WW + nx * WW + ny];
    if (idx >= 0) g_dym[b * NLp + idx] = 1;
}

// ---------------------------------------------------------------------------
// Fused attention, both branches; warp per query pillar, compact output.
// ---------------------------------------------------------------------------
__global__ void attn_kernel(const int* __restrict__ li_c,
                            const int* __restrict__ ra_c)
{
    int gw   = (blockIdx.x * blockDim.x + threadIdx.x) >> 5;
    int lane = threadIdx.x & 31;
    if (gw >= BB * (NLp + NRp)) return;

    int branch1 = gw < BB * NLp;
    int p = branch1 ? gw : gw - BB * NLp;
    if (branch1 && !g_dym[p]) return;   // paint gates too; skip the work

    const Folded* f   = branch1 ? &g_f1 : &g_f2;
    const int*  coors = branch1 ? li_c : ra_c;
    const int*  grid  = branch1 ? g_grid_ra : g_grid_li;
    const float* qp   = branch1 ? g_qp1 : g_qp2;
    const float* kk   = branch1 ? g_kk1 : g_kk2;
    const float* vv   = branch1 ? g_vv1 : g_vv2;
    float* outc       = branch1 ? g_out1 : g_out2;
    int N = branch1 ? NLp : NRp;
    int M = branch1 ? NRp : NLp;

    int b  = p / N;
    int cx = coors[p * 2], cy = coors[p * 2 + 1];
    float q = qp[(size_t)p * CC + lane];
    const int*   gb  = grid + b * HH * WW;
    const float* kkb = kk + (size_t)b * M * CC;
    const float* vvb = vv + (size_t)b * M * CC;

    float sj[9], vpj[9];
    #pragma unroll
    for (int j = 0; j < 9; j++) {
        int nx = cx + SH9[j][0], ny = cy + SH9[j][1];
        int idx = -1;
        if ((unsigned)nx < HH && (unsigned)ny < WW) idx = gb[nx * WW + ny];
        float kp, vp;
        if (idx >= 0) {
            kp = kkb[(size_t)idx * CC + lane];
            vp = vvb[(size_t)idx * CC + lane] + f->pe9v[j * CC + lane];
        } else {
            kp = f->bki[lane];
            vp = f->bvi[lane];
        }
        float pr = q * kp;
        pr += __shfl_xor_sync(FULLMASK, pr, 8);
        pr += __shfl_xor_sync(FULLMASK, pr, 4);
        pr += __shfl_xor_sync(FULLMASK, pr, 2);
        pr += __shfl_xor_sync(FULLMASK, pr, 1);
        sj[j]  = pr * 0.25f;
        vpj[j] = vp;
    }

    float mx = sj[0];
    #pragma unroll
    for (int j = 1; j < 9; j++) mx = fmaxf(mx, sj[j]);
    float den = 0.f, o = 0.f;
    #pragma unroll
    for (int j = 0; j < 9; j++) {
        float e = expf(sj[j] - mx);
        den += e;
        o = fmaf(e, vpj[j], o);
    }
    o /= den;

    float acc = f->bo[lane];
    #pragma unroll
    for (int l = 0; l < CC; l++) {
        float ol = __shfl_sync(FULLMASK, o, l);
        acc = fmaf(f->WoT[l * CC + lane], ol, acc);
    }
    outc[(size_t)p * CC + lane] = acc;
}

// ---------------------------------------------------------------------------
// Paint: produce the full dense output with coalesced float4 stores.
// One block per (image, batch, row). Grid row cached in smem (dy-gated).
// ---------------------------------------------------------------------------
__global__ void paint_kernel(float* __restrict__ out)
{
    __shared__ int idxrow[WW];

    int bid = blockIdx.x;
    int x   = bid & (HH - 1);
    int b   = (bid >> 9) & (BB - 1);
    int img = bid >> 10;                 // 0 = lidar canvas, 1 = radar canvas
    int tid = threadIdx.x;               // 256 threads

    const int* grid = img ? g_grid_ra : g_grid_li;
    const float* vals = img ? g_out2 : g_out1;
    int N = img ? NRp : NLp;

    // load + gate one grid row
    #pragma unroll
    for (int k = 0; k < 2; k++) {
        int y = tid + k * 256;
        int idx = grid[b * HH * WW + x * WW + y];
        if (!img && idx >= 0 && !g_dym[b * NLp + idx]) idx = -1;
        idxrow[y] = idx;
    }
    __syncthreads();

    // 256 threads: tid>>7 selects channel offset (0/1), tid&127 selects y/4
    int y4 = (tid & 127) * 4;
    int cofs = tid >> 7;
    int i0 = idxrow[y4], i1 = idxrow[y4 + 1], i2 = idxrow[y4 + 2], i3 = idxrow[y4 + 3];

    size_t base = ((size_t)img * BB + b) * CC * (HH * WW) + (size_t)x * WW;
    const float* vb = vals + (size_t)b * N * CC;

    #pragma unroll
    for (int c0 = 0; c0 < CC; c0 += 2) {
        int c = c0 + cofs;
        float4 o;
        o.x = i0 >= 0 ? vb[(size_t)i0 * CC + c] : 0.f;
        o.y = i1 >= 0 ? vb[(size_t)i1 * CC + c] : 0.f;
        o.z = i2 >= 0 ? vb[(size_t)i2 * CC + c] : 0.f;
        o.w = i3 >= 0 ? vb[(size_t)i3 * CC + c] : 0.f;
        *(float4*)(out + base + (size_t)c * (HH * WW) + y4) = o;
    }
}

// ---------------------------------------------------------------------------
// Host launcher
// ---------------------------------------------------------------------------
extern "C" void kernel_launch(void* const* d_in, const int* in_sizes, int n_in,
                              void* d_out, int out_size)
{
    const float* li_f = (const float*)d_in[0];
    const int*   li_c = (const int*)d_in[1];
    const float* ra_f = (const float*)d_in[2];
    const int*   ra_c = (const int*)d_in[3];
    const void*  dy   = d_in[4];
    const float* ln_li_w = (const float*)d_in[5];
    const float* ln_li_b = (const float*)d_in[6];
    const float* ln_ra_w = (const float*)d_in[7];
    const float* ln_ra_b = (const float*)d_in[8];

    Params P;
    P.q1w = (const float*)d_in[9];   P.q1b = (const float*)d_in[10];
    P.k1w = (const float*)d_in[11];  P.k1b = (const float*)d_in[12];
    P.v1w = (const float*)d_in[13];  P.v1b = (const float*)d_in[14];
    P.q2w = (const float*)d_in[15];  P.q2b = (const float*)d_in[16];
    P.k2w = (const float*)d_in[17];  P.k2b = (const float*)d_in[18];
    P.v2w = (const float*)d_in[19];  P.v2b = (const float*)d_in[20];
    P.posw = (const float*)d_in[21]; P.posb = (const float*)d_in[22];
    P.a1iw = (const float*)d_in[23]; P.a1ib = (const float*)d_in[24];
    P.a1ow = (const float*)d_in[25]; P.a1ob = (const float*)d_in[26];
    P.a2iw = (const float*)d_in[27]; P.a2ib = (const float*)d_in[28];
    P.a2ow = (const float*)d_in[29]; P.a2ob = (const float*)d_in[30];

    prep_kernel<<<1, 1024>>>(P);
    dy_probe_kernel<<<10, 256>>>((const unsigned int*)dy);
    clear_kernel<<<(BB * HH * WW + 255) / 256, 256>>>();
    build_grid_kernel<<<(BB * (NLp + NRp) + 255) / 256, 256>>>(li_c, ra_c);
    proj_kernel<<<(BB * (NLp + NRp) * 32 + 255) / 256, 256>>>(
        li_f, ra_f, ln_li_w, ln_li_b, ln_ra_w, ln_ra_b);
    dy_kernel<<<(BB * NRp * 25 + 255) / 256, 256>>>(ra_c, dy);
    attn_kernel<<<(BB * (NLp + NRp) * 32 + 255) / 256, 256>>>(li_c, ra_c);
    paint_kernel<<<2 * BB * HH, 256>>>((float*)d_out);
}

// round 4
// speedup vs baseline: 1.0902x; 1.0017x over previous
#include <cuda_runtime.h>

#define HH  512
#define WW  512
#define CC  32
#define BB  2
#define NLp 50000
#define NRp 20000
#define EPSf 1e-5f
#define FULLMASK 0xffffffffu

// ---------------------------------------------------------------------------
// Folded parameter block per attention branch (matrices transposed [m][o]).
// ---------------------------------------------------------------------------
struct Folded {
    float WqT[CC * CC]; float bq[CC];
    float WkT[CC * CC]; float bkv[CC]; float bki[CC];
    float WvT[CC * CC]; float bvv[CC]; float bvi[CC];
    float pe9v[9 * CC];
    float WoT[CC * CC]; float bo[CC];
};

__device__ Folded g_f1, g_f2;
__device__ int   g_grid_li[BB * HH * WW];
__device__ int   g_grid_ra[BB * HH * WW];
__device__ float g_qp1[BB * (size_t)NLp * CC];
__device__ float g_kk2[BB * (size_t)NLp * CC];
__device__ float g_vv2[BB * (size_t)NLp * CC];
__device__ float g_qp2[BB * (size_t)NRp * CC];
__device__ float g_kk1[BB * (size_t)NRp * CC];
__device__ float g_vv1[BB * (size_t)NRp * CC];
__device__ float g_out1[BB * (size_t)NLp * CC];   // compact branch1 output
__device__ float g_out2[BB * (size_t)NRp * CC];   // compact branch2 output
__device__ unsigned char g_dym[BB * NLp];
__device__ unsigned int  g_dyflags;

__constant__ int SH9[9][2] = {
    {0,0},{-1,0},{1,0},{0,1},{-1,1},{1,1},{0,-1},{-1,-1},{1,-1}
};

struct Params {
    const float *q1w,*q1b,*k1w,*k1b,*v1w,*v1b;
    const float *q2w,*q2b,*k2w,*k2b,*v2w,*v2b;
    const float *posw,*posb;
    const float *a1iw,*a1ib,*a1ow,*a1ob;
    const float *a2iw,*a2ib,*a2ow,*a2ob;
};

__device__ void fold_branch(Folded* f,
                            const float* qw, const float* qb,
                            const float* kw, const float* kb,
                            const float* vw, const float* vb,
                            const float* inw, const float* inb,
                            const float* ow,  const float* ob,
                            const float* posw, const float* posb,
                            int o, int m)
{
    float aq = 0.f, ak = 0.f, av = 0.f;
    #pragma unroll
    for (int i = 0; i < CC; i++) {
        aq += inw[o * CC + i]            * qw[i * CC + m];
        ak += inw[(CC + o) * CC + i]     * kw[i * CC + m];
        av += inw[(2 * CC + o) * CC + i] * vw[i * CC + m];
    }
    f->WqT[m * CC + o] = aq;
    f->WkT[m * CC + o] = ak;
    f->WvT[m * CC + o] = av;
    f->WoT[m * CC + o] = ow[o * CC + m];

    if (m == 0) {
        float bq = inb[o], bk = inb[CC + o], bv = inb[2 * CC + o];
        #pragma unroll
        for (int i = 0; i < CC; i++) {
            bq += inw[o * CC + i]            * qb[i];
            bk += inw[(CC + o) * CC + i]     * kb[i];
            bv += inw[(2 * CC + o) * CC + i] * vb[i];
        }
        f->bq[o]  = bq;
        f->bkv[o] = bk;  f->bki[o] = inb[CC + o];
        f->bvv[o] = bv;  f->bvi[o] = inb[2 * CC + o];
        f->bo[o]  = ob[o];
    }
    if (m < 9) {
        float s0 = (float)SH9[m][0], s1 = (float)SH9[m][1];
        float acc = 0.f;
        #pragma unroll
        for (int i = 0; i < CC; i++) {
            float pe = s0 * posw[i * 2] + s1 * posw[i * 2 + 1] + posb[i];
            acc += inw[(2 * CC + o) * CC + i] * pe;
        }
        f->pe9v[m * CC + o] = acc;
    }
}

__global__ void prep_kernel(Params P)
{
    int tid = threadIdx.x;
    int o = tid >> 5, m = tid & 31;
    fold_branch(&g_f1, P.q1w, P.q1b, P.k1w, P.k1b, P.v1w, P.v1b,
                P.a1iw, P.a1ib, P.a1ow, P.a1ob, P.posw, P.posb, o, m);
    fold_branch(&g_f2, P.q2w, P.q2b, P.k2w, P.k2b, P.v2w, P.v2b,
                P.a2iw, P.a2ib, P.a2ow, P.a2ob, P.posw, P.posb, o, m);
    if (tid == 0) g_dyflags = 0;
}

// dy dtype probe (see R1): classify bool buffer layout from its bytes.
__global__ void dy_probe_kernel(const unsigned int* __restrict__ p)
{
    unsigned int f = 0;
    for (int i = blockIdx.x * blockDim.x + threadIdx.x; i < (BB * NRp) / 4;
         i += blockDim.x * gridDim.x) {
        unsigned int w = p[i];
        unsigned int b0 = w & 0xffu, b1 = (w >> 8) & 0xffu,
                     b2 = (w >> 16) & 0xffu, b3 = (w >> 24) & 0xffu;
        if (b0 >= 2u || b1 >= 2u || b2 >= 2u || b3 >= 2u) f |= 1u;
        if ((w & 0xffffff00u) != 0u) f |= 2u;
    }
    if (f) atomicOr(&g_dyflags, f);
}

__global__ void clear_kernel()
{
    int i = blockIdx.x * blockDim.x + threadIdx.x;
    if (i < BB * HH * WW) { g_grid_li[i] = -1; g_grid_ra[i] = -1; }
    if (i < BB * NLp) g_dym[i] = 0;
}

// Fused: first BB*NLp threads build lidar grid, rest build radar grid.
__global__ void build_grid_kernel(const int* __restrict__ li_c,
                                  const int* __restrict__ ra_c)
{
    int i = blockIdx.x * blockDim.x + threadIdx.x;
    if (i < BB * NLp) {
        int b = i / NLp;
        g_grid_li[b * HH * WW + li_c[i * 2] * WW + li_c[i * 2 + 1]] = i - b * NLp;
    } else if (i < BB * (NLp + NRp)) {
        int j = i - BB * NLp;
        int b = j / NRp;
        g_grid_ra[b * HH * WW + ra_c[j * 2] * WW + ra_c[j * 2 + 1]] = j - b * NRp;
    }
}

// ---------------------------------------------------------------------------
// Fused LN + 3 folded matvecs for both modalities; warp per pillar.
// ---------------------------------------------------------------------------
__global__ void proj_kernel(const float* __restrict__ li_f,
                            const float* __restrict__ ra_f,
                            const float* __restrict__ ln_li_w,
                            const float* __restrict__ ln_li_b,
                            const float* __restrict__ ln_ra_w,
                            const float* __restrict__ ln_ra_b)
{
    int gw   = (blockIdx.x * blockDim.x + threadIdx.x) >> 5;
    int lane = threadIdx.x & 31;
    if (gw >= BB * (NLp + NRp)) return;

    int lidar = gw < BB * NLp;
    int p = lidar ? gw : gw - BB * NLp;

    const float* feats = lidar ? li_f : ra_f;
    const float* lnw   = lidar ? ln_li_w : ln_ra_w;
    const float* lnb   = lidar ? ln_li_b : ln_ra_b;
    const Folded* fq   = lidar ? &g_f1 : &g_f2;
    const Folded* fkv  = lidar ? &g_f2 : &g_f1;
    float* qp = lidar ? g_qp1 : g_qp2;
    float* kk = lidar ? g_kk2 : g_kk1;
    float* vv = lidar ? g_vv2 : g_vv1;

    float v = feats[(size_t)p * CC + lane];
    float s = v;
    #pragma unroll
    for (int off = 16; off; off >>= 1) s += __shfl_xor_sync(FULLMASK, s, off);
    float mu = s * (1.f / 32.f);
    float d  = v - mu;
    float ss = d * d;
    #pragma unroll
    for (int off = 16; off; off >>= 1) ss += __shfl_xor_sync(FULLMASK, ss, off);
    float xn = d * rsqrtf(ss * (1.f / 32.f) + EPSf) * lnw[lane] + lnb[lane];

    float aq = fq->bq[lane], ak = fkv->bkv[lane], av = fkv->bvv[lane];
    #pragma unroll
    for (int m = 0; m < CC; m++) {
        float xm = __shfl_sync(FULLMASK, xn, m);
        aq = fmaf(fq->WqT[m * CC + lane],  xm, aq);
        ak = fmaf(fkv->WkT[m * CC + lane], xm, ak);
        av = fmaf(fkv->WvT[m * CC + lane], xm, av);
    }
    size_t o = (size_t)p * CC + lane;
    qp[o] = aq; kk[o] = ak; vv[o] = av;
}

// ---------------------------------------------------------------------------
// Dynamic-lidar mask (5x5 window, mod-(H+1,W+1) wraparound quirk preserved).
// ---------------------------------------------------------------------------
__global__ void dy_kernel(const int* __restrict__ ra_coors,
                          const void* __restrict__ dy)
{
    int t = blockIdx.x * blockDim.x + threadIdx.x;
    if (t >= BB * NRp * 25) return;
    int s = t % 25;
    int r = t / 25;

    unsigned int flags = g_dyflags;
    bool is_dy;
    if (flags & 1u)      is_dy = ((const unsigned int*)dy)[r] != 0u;
    else if (flags & 2u) is_dy = ((const unsigned char*)dy)[r] != 0;
    else                 is_dy = ((const unsigned int*)dy)[r] != 0u;
    if (!is_dy) return;

    int b  = r / NRp;
    int nx = ra_coors[r * 2]     + (s / 5) - 2;
    int ny = ra_coors[r * 2 + 1] + (s % 5) - 2;
    nx = nx < 0 ? nx + (HH + 1) : (nx >= (HH + 1) ? nx - (HH + 1) : nx);
    ny = ny < 0 ? ny + (WW + 1) : (ny >= (WW + 1) ? ny - (WW + 1) : ny);
    if (nx >= HH || ny >= WW) return;
    int idx = g_grid_li[b * HH * WW + nx * WW + ny];
    if (idx >= 0) g_dym[b * NLp + idx] = 1;
}

// ---------------------------------------------------------------------------
// Fused attention, both branches; warp per query pillar, compact output.
// ---------------------------------------------------------------------------
__global__ void attn_kernel(const int* __restrict__ li_c,
                            const int* __restrict__ ra_c)
{
    int gw   = (blockIdx.x * blockDim.x + threadIdx.x) >> 5;
    int lane = threadIdx.x & 31;
    if (gw >= BB * (NLp + NRp)) return;

    int branch1 = gw < BB * NLp;
    int p = branch1 ? gw : gw - BB * NLp;
    if (branch1 && !g_dym[p]) return;   // paint gates too; skip the work

    const Folded* f   = branch1 ? &g_f1 : &g_f2;
    const int*  coors = branch1 ? li_c : ra_c;
    const int*  grid  = branch1 ? g_grid_ra : g_grid_li;
    const float* qp   = branch1 ? g_qp1 : g_qp2;
    const float* kk   = branch1 ? g_kk1 : g_kk2;
    const float* vv   = branch1 ? g_vv1 : g_vv2;
    float* outc       = branch1 ? g_out1 : g_out2;
    int N = branch1 ? NLp : NRp;
    int M = branch1 ? NRp : NLp;

    int b  = p / N;
    int cx = coors[p * 2], cy = coors[p * 2 + 1];
    float q = qp[(size_t)p * CC + lane];
    const int*   gb  = grid + b * HH * WW;
    const float* kkb = kk + (size_t)b * M * CC;
    const float* vvb = vv + (size_t)b * M * CC;

    float sj[9], vpj[9];
    #pragma unroll
    for (int j = 0; j < 9; j++) {
        int nx = cx + SH9[j][0], ny = cy + SH9[j][1];
        int idx = -1;
        if ((unsigned)nx < HH && (unsigned)ny < WW) idx = gb[nx * WW + ny];
        float kp, vp;
        if (idx >= 0) {
            kp = kkb[(size_t)idx * CC + lane];
            vp = vvb[(size_t)idx * CC + lane] + f->pe9v[j * CC + lane];
        } else {
            kp = f->bki[lane];
            vp = f->bvi[lane];
        }
        float pr = q * kp;
        pr += __shfl_xor_sync(FULLMASK, pr, 8);
        pr += __shfl_xor_sync(FULLMASK, pr, 4);
        pr += __shfl_xor_sync(FULLMASK, pr, 2);
        pr += __shfl_xor_sync(FULLMASK, pr, 1);
        sj[j]  = pr * 0.25f;
        vpj[j] = vp;
    }

    float mx = sj[0];
    #pragma unroll
    for (int j = 1; j < 9; j++) mx = fmaxf(mx, sj[j]);
    float den = 0.f, o = 0.f;
    #pragma unroll
    for (int j = 0; j < 9; j++) {
        float e = expf(sj[j] - mx);
        den += e;
        o = fmaf(e, vpj[j], o);
    }
    o /= den;

    float acc = f->bo[lane];
    #pragma unroll
    for (int l = 0; l < CC; l++) {
        float ol = __shfl_sync(FULLMASK, o, l);
        acc = fmaf(f->WoT[l * CC + lane], ol, acc);
    }
    outc[(size_t)p * CC + lane] = acc;
}

// ---------------------------------------------------------------------------
// Paint: produce the full dense output with coalesced float4 stores.
// One block per (image, batch, row). Grid row cached in smem (dy-gated).
// ---------------------------------------------------------------------------
__global__ void paint_kernel(float* __restrict__ out)
{
    __shared__ int idxrow[WW];

    int bid = blockIdx.x;
    int x   = bid & (HH - 1);
    int b   = (bid >> 9) & (BB - 1);
    int img = bid >> 10;                 // 0 = lidar canvas, 1 = radar canvas
    int tid = threadIdx.x;               // 256 threads

    const int* grid = img ? g_grid_ra : g_grid_li;
    const float* vals = img ? g_out2 : g_out1;
    int N = img ? NRp : NLp;

    // load + gate one grid row
    #pragma unroll
    for (int k = 0; k < 2; k++) {
        int y = tid + k * 256;
        int idx = grid[b * HH * WW + x * WW + y];
        if (!img && idx >= 0 && !g_dym[b * NLp + idx]) idx = -1;
        idxrow[y] = idx;
    }
    __syncthreads();

    // 256 threads: tid>>7 selects channel offset (0/1), tid&127 selects y/4
    int y4 = (tid & 127) * 4;
    int cofs = tid >> 7;
    int i0 = idxrow[y4], i1 = idxrow[y4 + 1], i2 = idxrow[y4 + 2], i3 = idxrow[y4 + 3];

    size_t base = ((size_t)img * BB + b) * CC * (HH * WW) + (size_t)x * WW;
    const float* vb = vals + (size_t)b * N * CC;

    #pragma unroll
    for (int c0 = 0; c0 < CC; c0 += 2) {
        int c = c0 + cofs;
        float4 o;
        o.x = i0 >= 0 ? vb[(size_t)i0 * CC + c] : 0.f;
        o.y = i1 >= 0 ? vb[(size_t)i1 * CC + c] : 0.f;
        o.z = i2 >= 0 ? vb[(size_t)i2 * CC + c] : 0.f;
        o.w = i3 >= 0 ? vb[(size_t)i3 * CC + c] : 0.f;
        *(float4*)(out + base + (size_t)c * (HH * WW) + y4) = o;
    }
}

// ---------------------------------------------------------------------------
// Host launcher
// ---------------------------------------------------------------------------
extern "C" void kernel_launch(void* const* d_in, const int* in_sizes, int n_in,
                              void* d_out, int out_size)
{
    const float* li_f = (const float*)d_in[0];
    const int*   li_c = (const int*)d_in[1];
    const float* ra_f = (const float*)d_in[2];
    const int*   ra_c = (const int*)d_in[3];
    const void*  dy   = d_in[4];
    const float* ln_li_w = (const float*)d_in[5];
    const float* ln_li_b = (const float*)d_in[6];
    const float* ln_ra_w = (const float*)d_in[7];
    const float* ln_ra_b = (const float*)d_in[8];

    Params P;
    P.q1w = (const float*)d_in[9];   P.q1b = (const float*)d_in[10];
    P.k1w = (const float*)d_in[11];  P.k1b = (const float*)d_in[12];
    P.v1w = (const float*)d_in[13];  P.v1b = (const float*)d_in[14];
    P.q2w = (const float*)d_in[15];  P.q2b = (const float*)d_in[16];
    P.k2w = (const float*)d_in[17];  P.k2b = (const float*)d_in[18];
    P.v2w = (const float*)d_in[19];  P.v2b = (const float*)d_in[20];
    P.posw = (const float*)d_in[21]; P.posb = (const float*)d_in[22];
    P.a1iw = (const float*)d_in[23]; P.a1ib = (const float*)d_in[24];
    P.a1ow = (const float*)d_in[25]; P.a1ob = (const float*)d_in[26];
    P.a2iw = (const float*)d_in[27]; P.a2ib = (const float*)d_in[28];
    P.a2ow = (const float*)d_in[29]; P.a2ob = (const float*)d_in[30];

    prep_kernel<<<1, 1024>>>(P);
    dy_probe_kernel<<<10, 256>>>((const unsigned int*)dy);
    clear_kernel<<<(BB * HH * WW + 255) / 256, 256>>>();
    build_grid_kernel<<<(BB * (NLp + NRp) + 255) / 256, 256>>>(li_c, ra_c);
    proj_kernel<<<(BB * (NLp + NRp) * 32 + 255) / 256, 256>>>(
        li_f, ra_f, ln_li_w, ln_li_b, ln_ra_w, ln_ra_b);
    dy_kernel<<<(BB * NRp * 25 + 255) / 256, 256>>>(ra_c, dy);
    attn_kernel<<<(BB * (NLp + NRp) * 32 + 255) / 256, 256>>>(li_c, ra_c);
    paint_kernel<<<2 * BB * HH, 256>>>((float*)d_out);
}